// round 14
// baseline (speedup 1.0000x reference)
#include <cuda_runtime.h>
#include <cuda_bf16.h>

#define MAX_N 100000
#define MAX_E 1600000
#define IN_F 128
#define EDGE_F 16
#define SCAN_BLK 1024
#define MAX_SCAN_BLOCKS 128
#define N_PAD (MAX_N + 128)
#define WPR 64            // 32-bit words per activation row (128 bf16)
#define WW 192            // packed words per weight row (K=384)

// ---------------- static device scratch (allocation-free rule) --------------
__device__ __align__(16) int  g_cnt[MAX_N];
__device__ __align__(16) int  g_off[MAX_N];
__device__ __align__(16) int  g_cur[MAX_N];
__device__ __align__(16) int  g_bsum[MAX_SCAN_BLOCKS];
__device__ __align__(16) int  g_bbase[MAX_SCAN_BLOCKS];
__device__ __align__(16) int2 g_edges[MAX_E];
// Activations, hi/lo split, fragment-permuted word layout (see perm_w)
__device__ __align__(16) unsigned g_Ahp[(size_t)N_PAD * WPR];
__device__ __align__(16) unsigned g_Alp[(size_t)N_PAD * WPR];
// Weights, linearized K=384 = [Wh | Wh | Wl], [n][192] packed bf16x2 words
__device__ __align__(16) unsigned g_W1p[IN_F * WW];
__device__ __align__(16) unsigned g_W2p[IN_F * WW];
__device__ int g_idx64;

// ------------------------------- helpers ------------------------------------
__device__ __forceinline__ unsigned cvt_bf16x2(float hi, float lo) {
    unsigned r; asm("cvt.rn.bf16x2.f32 %0, %1, %2;" : "=r"(r) : "f"(hi), "f"(lo));
    return r;
}
__device__ __forceinline__ float bflo_f(unsigned p) { return __uint_as_float(p << 16); }
__device__ __forceinline__ float bfhi_f(unsigned p) { return __uint_as_float(p & 0xffff0000u); }

// in-group word permutation: word w (cols 2w,2w+1) -> slot so that fragment
// pairs (k, k+8) sit in adjacent 32-bit words (one LDG.64 per fragment pair)
__device__ __forceinline__ int perm_w(int w) {
    int ww = w & 7;
    return (w & ~7) + ((ww < 4) ? (2 * ww) : (2 * (ww - 4) + 1));
}

__device__ __forceinline__ void mma16816(float c[4],
                                         unsigned a0, unsigned a1, unsigned a2, unsigned a3,
                                         unsigned b0, unsigned b1) {
    asm volatile(
        "mma.sync.aligned.m16n8k16.row.col.f32.bf16.bf16.f32 "
        "{%0,%1,%2,%3}, {%4,%5,%6,%7}, {%8,%9}, {%0,%1,%2,%3};"
        : "+f"(c[0]), "+f"(c[1]), "+f"(c[2]), "+f"(c[3])
        : "r"(a0), "r"(a1), "r"(a2), "r"(a3), "r"(b0), "r"(b1));
}

__device__ __forceinline__ int load_idx(const void* ei, size_t pos, int is64) {
    if (is64) return (int)(reinterpret_cast<const long long*>(ei)[pos]);
    return reinterpret_cast<const int*>(ei)[pos];
}

// ---------------------------------------------------------------------------
// 0) fused init: dtype detect + zero histogram + pack/split weights
__global__ void k_init(const int* __restrict__ ei_raw,
                       const float* __restrict__ W1, const float* __restrict__ W2,
                       int N) {
    int i = blockIdx.x * blockDim.x + threadIdx.x;

    if (blockIdx.x == 0 && threadIdx.x < 32) {
        int lane = threadIdx.x;
        int nz = 0;
        for (int j = lane; j < 128; j += 32) nz |= ei_raw[2 * j + 1];
        unsigned b = __ballot_sync(0xffffffffu, nz != 0);
        if (lane == 0) g_idx64 = (b == 0) ? 1 : 0;
    }

    if (i < N) g_cnt[i] = 0;

    if (i < IN_F * WW) {
        int n = i / WW, kw = i % WW;
        int seg = kw >> 6;              // 0,1 -> hi ; 2 -> lo
        int k0 = (kw & 63) * 2;
        int pos = perm_w(kw & 63) + (kw & ~63);  // permute within 64-word segment
        // NOTE: perm is within 8-word groups; segment base preserved:
        pos = (kw & ~7) + ((kw & 7) < 4 ? 2 * (kw & 7) : 2 * ((kw & 7) - 4) + 1);

        float w0 = W1[k0 * IN_F + n], w1 = W1[(k0 + 1) * IN_F + n];
        __nv_bfloat16 h0 = __float2bfloat16(w0), h1 = __float2bfloat16(w1);
        unsigned val;
        if (seg == 2) {
            __nv_bfloat16 l0 = __float2bfloat16(w0 - __bfloat162float(h0));
            __nv_bfloat16 l1 = __float2bfloat16(w1 - __bfloat162float(h1));
            val = ((unsigned)__bfloat16_as_ushort(l1) << 16) | __bfloat16_as_ushort(l0);
        } else {
            val = ((unsigned)__bfloat16_as_ushort(h1) << 16) | __bfloat16_as_ushort(h0);
        }
        g_W1p[n * WW + pos] = val;

        w0 = W2[k0 * IN_F + n]; w1 = W2[(k0 + 1) * IN_F + n];
        h0 = __float2bfloat16(w0); h1 = __float2bfloat16(w1);
        if (seg == 2) {
            __nv_bfloat16 l0 = __float2bfloat16(w0 - __bfloat162float(h0));
            __nv_bfloat16 l1 = __float2bfloat16(w1 - __bfloat162float(h1));
            val = ((unsigned)__bfloat16_as_ushort(l1) << 16) | __bfloat16_as_ushort(l0);
        } else {
            val = ((unsigned)__bfloat16_as_ushort(h1) << 16) | __bfloat16_as_ushort(h0);
        }
        g_W2p[n * WW + pos] = val;
    }
}

// ---------------------------------------------------------------------------
__global__ void k_hist(const void* __restrict__ ei, int E) {
    int e = blockIdx.x * blockDim.x + threadIdx.x;
    int is64 = g_idx64;
    if (e < E) {
        int dst = load_idx(ei, (size_t)E + e, is64);
        atomicAdd(&g_cnt[dst], 1);
    }
}

__global__ void k_scanA(int N) {
    __shared__ int s[SCAN_BLK];
    int t = threadIdx.x;
    int idx = blockIdx.x * SCAN_BLK + t;
    int v = (idx < N) ? g_cnt[idx] : 0;
    s[t] = v;
    __syncthreads();
    for (int off = 1; off < SCAN_BLK; off <<= 1) {
        int add = (t >= off) ? s[t - off] : 0;
        __syncthreads();
        s[t] += add;
        __syncthreads();
    }
    if (idx < N) g_off[idx] = s[t] - v;
    if (t == SCAN_BLK - 1) g_bsum[blockIdx.x] = s[t];
}

__global__ void k_scanB(int nb) {
    __shared__ int s[MAX_SCAN_BLOCKS];
    int t = threadIdx.x;
    int v = (t < nb) ? g_bsum[t] : 0;
    s[t] = v;
    __syncthreads();
    for (int off = 1; off < MAX_SCAN_BLOCKS; off <<= 1) {
        int add = (t >= off) ? s[t - off] : 0;
        __syncthreads();
        s[t] += add;
        __syncthreads();
    }
    if (t < nb) g_bbase[t] = s[t] - v;
}

__global__ void k_initcur(int N) {
    int i = blockIdx.x * blockDim.x + threadIdx.x;
    if (i < N) {
        int base = g_off[i] + g_bbase[i >> 10];
        g_off[i] = base;
        g_cur[i] = base;
    }
}

__global__ void k_scatter(const void* __restrict__ ei, int E) {
    int e = blockIdx.x * blockDim.x + threadIdx.x;
    int is64 = g_idx64;
    if (e < E) {
        int src = load_idx(ei, (size_t)e, is64);
        int dst = load_idx(ei, (size_t)E + e, is64);
        int p = atomicAdd(&g_cur[dst], 1);
        g_edges[p] = make_int2(src, e);
    }
}

// ---------------------------------------------------------------------------
// warp-per-node gather -> permuted split-bf16 activations
__global__ void __launch_bounds__(256)
k_gather(const float* __restrict__ H, const float* __restrict__ EA,
         const float* __restrict__ We, const float* __restrict__ be, int N) {
    int warp = (int)((blockIdx.x * (size_t)blockDim.x + threadIdx.x) >> 5);
    int lane = threadIdx.x & 31;
    if (warp >= N) return;

    int start = g_off[warp];
    int d = g_cnt[warp];

    float4 accH = make_float4(0.f, 0.f, 0.f, 0.f);
    float eaSum = 0.f;

    const int2* ep = g_edges + start;
    const float4* H4 = reinterpret_cast<const float4*>(H);

    int i = 0;
    for (; i + 4 <= d; i += 4) {
        int2 e0 = ep[i], e1 = ep[i + 1], e2 = ep[i + 2], e3 = ep[i + 3];
        float4 h0 = H4[(size_t)e0.x * 32 + lane];
        float4 h1 = H4[(size_t)e1.x * 32 + lane];
        float4 h2 = H4[(size_t)e2.x * 32 + lane];
        float4 h3 = H4[(size_t)e3.x * 32 + lane];
        float a0 = 0.f, a1 = 0.f, a2 = 0.f, a3 = 0.f;
        if (lane < EDGE_F) {
            a0 = EA[(size_t)e0.y * EDGE_F + lane];
            a1 = EA[(size_t)e1.y * EDGE_F + lane];
            a2 = EA[(size_t)e2.y * EDGE_F + lane];
            a3 = EA[(size_t)e3.y * EDGE_F + lane];
        }
        accH.x += (h0.x + h1.x) + (h2.x + h3.x);
        accH.y += (h0.y + h1.y) + (h2.y + h3.y);
        accH.z += (h0.z + h1.z) + (h2.z + h3.z);
        accH.w += (h0.w + h1.w) + (h2.w + h3.w);
        eaSum += (a0 + a1) + (a2 + a3);
    }
    for (; i < d; i++) {
        int2 se = ep[i];
        float4 hv = H4[(size_t)se.x * 32 + lane];
        accH.x += hv.x; accH.y += hv.y; accH.z += hv.z; accH.w += hv.w;
        if (lane < EDGE_F)
            eaSum += EA[(size_t)se.y * EDGE_F + lane];
    }

    float4 a = accH;
    #pragma unroll
    for (int k = 0; k < EDGE_F; k++) {
        float ek = __shfl_sync(0xffffffffu, eaSum, k);
        float4 w = reinterpret_cast<const float4*>(We + k * IN_F)[lane];
        a.x += ek * w.x; a.y += ek * w.y; a.z += ek * w.z; a.w += ek * w.w;
    }
    float degf = (float)d;
    float4 bv = reinterpret_cast<const float4*>(be)[lane];
    a.x += degf * bv.x; a.y += degf * bv.y; a.z += degf * bv.z; a.w += degf * bv.w;

    // hi/lo split; word w0 = cols (4l,4l+1), w1 = cols (4l+2,4l+3)
    unsigned ph0 = cvt_bf16x2(a.y, a.x);
    unsigned ph1 = cvt_bf16x2(a.w, a.z);
    unsigned pl0 = cvt_bf16x2(a.y - bfhi_f(ph0), a.x - bflo_f(ph0));
    unsigned pl1 = cvt_bf16x2(a.w - bfhi_f(ph1), a.z - bflo_f(ph1));

    size_t rb = (size_t)warp * WPR;
    int p0 = perm_w(2 * lane), p1 = perm_w(2 * lane + 1);
    g_Ahp[rb + p0] = ph0;
    g_Ahp[rb + p1] = ph1;
    g_Alp[rb + p0] = pl0;
    g_Alp[rb + p1] = pl1;
}

// ---------------------------------------------------------------------------
// Tensor-core MLP via mma.sync, linearized K=384 split-bf16.
// Block = 64 rows / 4 warps; warp owns 16 rows x 128 cols.
// All fragment loads are LDG.64 thanks to the permuted layouts.
// ---------------------------------------------------------------------------
__global__ void __launch_bounds__(128)
k_mma(const float* __restrict__ b1, const float* __restrict__ b2,
      float* __restrict__ out, int N) {
    const int warp = threadIdx.x >> 5;
    const int lane = threadIdx.x & 31;
    const int g = lane >> 2;
    const int t = lane & 3;
    const int row0 = blockIdx.x * 64 + warp * 16;
    const int rowA = row0 + g, rowB = row0 + g + 8;

    float c[16][4];

    // ---- GEMM1: C = Abig @ W1big^T + b1 ----
    #pragma unroll
    for (int nt = 0; nt < 16; nt++) {
        float v0 = b1[nt * 8 + 2 * t], v1 = b1[nt * 8 + 2 * t + 1];
        c[nt][0] = v0; c[nt][1] = v1; c[nt][2] = v0; c[nt][3] = v1;
    }

    {
        const size_t rA = (size_t)rowA * WPR, rB = (size_t)rowB * WPR;
        for (int ks = 0; ks < 24; ks++) {
            int ksl = ks & 7;
            const unsigned* Ap = (ks >= 8 && ks < 16) ? g_Alp : g_Ahp;
            uint2 pA = *reinterpret_cast<const uint2*>(Ap + rA + ksl * 8 + 2 * t);
            uint2 pB = *reinterpret_cast<const uint2*>(Ap + rB + ksl * 8 + 2 * t);
            const unsigned* wbase = g_W1p + ks * 8 + 2 * t;
            #pragma unroll
            for (int nt = 0; nt < 16; nt++) {
                uint2 wv = *reinterpret_cast<const uint2*>(wbase + (nt * 8 + g) * WW);
                mma16816(c[nt], pA.x, pB.x, pA.y, pB.y, wv.x, wv.y);
            }
        }
    }

    // ---- relu + in-register split to GEMM2 A-fragments ----
    unsigned hh[16][2], hl[16][2];
    #pragma unroll
    for (int nt = 0; nt < 16; nt++) {
        float r0 = fmaxf(c[nt][0], 0.f), r1 = fmaxf(c[nt][1], 0.f);
        float r2 = fmaxf(c[nt][2], 0.f), r3 = fmaxf(c[nt][3], 0.f);
        unsigned p0 = cvt_bf16x2(r1, r0);
        unsigned p1 = cvt_bf16x2(r3, r2);
        hh[nt][0] = p0;
        hh[nt][1] = p1;
        hl[nt][0] = cvt_bf16x2(r1 - bfhi_f(p0), r0 - bflo_f(p0));
        hl[nt][1] = cvt_bf16x2(r3 - bfhi_f(p1), r2 - bflo_f(p1));
    }

    // ---- GEMM2: C = [hh|hl|hh] @ W2big^T + b2 ----
    #pragma unroll
    for (int nt = 0; nt < 16; nt++) {
        float v0 = b2[nt * 8 + 2 * t], v1 = b2[nt * 8 + 2 * t + 1];
        c[nt][0] = v0; c[nt][1] = v1; c[nt][2] = v0; c[nt][3] = v1;
    }

    #pragma unroll
    for (int ks = 0; ks < 8; ks++) {
        const unsigned* wbase = g_W2p + ks * 8 + 2 * t;
        #pragma unroll
        for (int nt = 0; nt < 16; nt++) {
            uint2 wv = *reinterpret_cast<const uint2*>(wbase + (nt * 8 + g) * WW);
            mma16816(c[nt], hh[2 * ks][0], hh[2 * ks][1],
                     hh[2 * ks + 1][0], hh[2 * ks + 1][1], wv.x, wv.y);
        }
    }
    #pragma unroll
    for (int ks = 0; ks < 8; ks++) {
        const unsigned* wbase = g_W2p + 64 + ks * 8 + 2 * t;
        #pragma unroll
        for (int nt = 0; nt < 16; nt++) {
            uint2 wv = *reinterpret_cast<const uint2*>(wbase + (nt * 8 + g) * WW);
            mma16816(c[nt], hl[2 * ks][0], hl[2 * ks][1],
                     hl[2 * ks + 1][0], hl[2 * ks + 1][1], wv.x, wv.y);
        }
    }
    #pragma unroll
    for (int ks = 0; ks < 8; ks++) {
        const unsigned* wbase = g_W2p + 128 + ks * 8 + 2 * t;
        #pragma unroll
        for (int nt = 0; nt < 16; nt++) {
            uint2 wv = *reinterpret_cast<const uint2*>(wbase + (nt * 8 + g) * WW);
            mma16816(c[nt], hh[2 * ks][0], hh[2 * ks][1],
                     hh[2 * ks + 1][0], hh[2 * ks + 1][1], wv.x, wv.y);
        }
    }

    // ---- epilogue ----
    #pragma unroll
    for (int nt = 0; nt < 16; nt++) {
        int colp = nt * 8 + 2 * t;
        if (rowA < N)
            *reinterpret_cast<float2*>(out + (size_t)rowA * IN_F + colp) =
                make_float2(c[nt][0], c[nt][1]);
        if (rowB < N)
            *reinterpret_cast<float2*>(out + (size_t)rowB * IN_F + colp) =
                make_float2(c[nt][2], c[nt][3]);
    }
}

// ---------------------------------------------------------------------------
extern "C" void kernel_launch(void* const* d_in, const int* in_sizes, int n_in,
                              void* d_out, int out_size) {
    const float* H  = (const float*)d_in[0];
    const void*  ei = d_in[1];
    const float* EA = (const float*)d_in[2];
    const float* We = (const float*)d_in[3];
    const float* be = (const float*)d_in[4];
    const float* W1 = (const float*)d_in[5];
    const float* b1 = (const float*)d_in[6];
    const float* W2 = (const float*)d_in[7];
    const float* b2 = (const float*)d_in[8];
    float* out = (float*)d_out;

    int N = in_sizes[0] / IN_F;
    int E = in_sizes[2] / EDGE_F;
    int nScanBlocks = (N + SCAN_BLK - 1) / SCAN_BLK;
    int initBlocks = ((N > IN_F * WW ? N : IN_F * WW) + 255) / 256;

    k_init<<<initBlocks, 256>>>((const int*)ei, W1, W2, N);
    k_hist<<<(E + 255) / 256, 256>>>(ei, E);
    k_scanA<<<nScanBlocks, SCAN_BLK>>>(N);
    k_scanB<<<1, MAX_SCAN_BLOCKS>>>(nScanBlocks);
    k_initcur<<<(N + 255) / 256, 256>>>(N);
    k_scatter<<<(E + 255) / 256, 256>>>(ei, E);

    int gblocks = (N + 7) / 8;
    k_gather<<<gblocks, 256>>>(H, EA, We, be, N);

    k_mma<<<(N + 63) / 64, 128>>>(b1, b2, out, N);
}